// round 1
// baseline (speedup 1.0000x reference)
#include <cuda_runtime.h>
#include <math.h>

// Problem shape (fixed by setup_inputs)
#define BH     64
#define MSEQ   1024
#define DIM    64
#define LSPAN  1024

#define BM     64        // query rows per CTA
#define BL     64        // l-tile width
#define KROWS  128       // BM + BL band rows per tile

#define QT_STRIDE 68
#define KT_STRIDE 132
#define PS_STRIDE 68
#define WT_STRIDE 68

// smem layout (floats):
//  Qt : 64 * 68            = 4352
//  KV : max(64*132, 128*64)= 8448   (Kt transposed  /  Vs row-major union)
//  Ps : 64 * 68            = 4352
//  Wt : 128 * 68           = 8704   (skewed exp-weights, transposed [k][i])
#define SMEM_FLOATS (4352 + 8448 + 4352 + 8704)

__global__ void __launch_bounds__(256, 2) seqattn_kernel(
    const float* __restrict__ Q,   // [BH, MSEQ, DIM]
    const float* __restrict__ K,   // [BH, MSEQ+LSPAN, DIM]
    const float* __restrict__ V,   // [BH, MSEQ+LSPAN, DIM]
    const float* __restrict__ P,   // [1, DIM, LSPAN]
    float* __restrict__ O)         // [BH, MSEQ, DIM]
{
    extern __shared__ float smem[];
    float* Qt = smem;                       // [64][QT_STRIDE]
    float* KV = Qt + 64 * QT_STRIDE;        // union: Kt [64][KT_STRIDE] / Vs [128][64]
    float* Ps = KV + 8448;                  // [64][PS_STRIDE]
    float* Wt = Ps + 64 * PS_STRIDE;        // [128][WT_STRIDE]

    const int tid = threadIdx.x;
    const int tx  = tid & 15;               // 16 cols of thread grid
    const int ty  = tid >> 4;               // 16 rows of thread grid
    const int bh  = blockIdx.y;
    const int m0  = blockIdx.x * BM;

    const float* Qg = Q + ((size_t)bh * MSEQ + m0) * DIM;
    const float* Kg = K + (size_t)bh * (MSEQ + LSPAN) * DIM;
    const float* Vg = V + (size_t)bh * (MSEQ + LSPAN) * DIM;

    // ---- load Q transposed: Qt[d][i] ----
    {
        const int j0 = tid >> 6;            // 0..3
        const int d  = tid & 63;
        #pragma unroll
        for (int p = 0; p < 16; p++) {
            int row = p * 4 + j0;
            Qt[d * QT_STRIDE + row] = Qg[row * DIM + d];
        }
    }

    float acc_o[4][4];
    float m_run[4], l_run[4];
    #pragma unroll
    for (int a = 0; a < 4; a++) {
        m_run[a] = -INFINITY; l_run[a] = 0.f;
        #pragma unroll
        for (int b = 0; b < 4; b++) acc_o[a][b] = 0.f;
    }

    for (int lt = 0; lt < LSPAN / BL; lt++) {
        __syncthreads();   // prev tile's PV done -> KV/Wt reusable

        // ---- load K band transposed: Kt[d][j], j in [0,128) ----
        {
            const int j0 = tid >> 6;
            const int d  = tid & 63;
            const float* src = Kg + (size_t)(m0 + lt * BL) * DIM + d;
            #pragma unroll
            for (int p = 0; p < 32; p++) {
                int j = p * 4 + j0;
                KV[d * KT_STRIDE + j] = src[(size_t)j * DIM];
            }
        }
        // ---- load Ps[d][l'] (float4) ----
        {
            const int d0 = tid >> 4;        // 0..15
            const int l4 = tid & 15;
            #pragma unroll
            for (int p = 0; p < 4; p++) {
                int dd = p * 16 + d0;
                float4 v = *(const float4*)(P + (size_t)dd * LSPAN + lt * BL + l4 * 4);
                *(float4*)(Ps + dd * PS_STRIDE + l4 * 4) = v;
            }
        }
        __syncthreads();

        // ---- S tile: s[i][l'] = sum_d q[i][d] * (k[i+l'][d] + p[d][l']) ----
        float acc[4][4];
        #pragma unroll
        for (int a = 0; a < 4; a++)
            #pragma unroll
            for (int b = 0; b < 4; b++) acc[a][b] = 0.f;

        const int kbase = 4 * (tx + ty);
        #pragma unroll 4
        for (int d = 0; d < DIM; d++) {
            float4 qv = *(const float4*)(Qt + d * QT_STRIDE + ty * 4);
            float4 pv = *(const float4*)(Ps + d * PS_STRIDE + tx * 4);
            float4 k0 = *(const float4*)(KV + d * KT_STRIDE + kbase);
            float4 k1 = *(const float4*)(KV + d * KT_STRIDE + kbase + 4);
            float kk[8] = {k0.x,k0.y,k0.z,k0.w,k1.x,k1.y,k1.z,k1.w};
            float qq[4] = {qv.x,qv.y,qv.z,qv.w};
            float pp[4] = {pv.x,pv.y,pv.z,pv.w};
            #pragma unroll
            for (int a = 0; a < 4; a++)
                #pragma unroll
                for (int b = 0; b < 4; b++)
                    acc[a][b] = fmaf(qq[a], kk[a + b] + pp[b], acc[a][b]);
        }

        // ---- online softmax + write skewed exp weights ----
        #pragma unroll
        for (int a = 0; a < 4; a++) {
            float tmax = acc[a][0];
            #pragma unroll
            for (int b = 1; b < 4; b++) tmax = fmaxf(tmax, acc[a][b]);
            tmax *= 0.125f;   // 1/sqrt(64)
            #pragma unroll
            for (int mm = 1; mm <= 8; mm <<= 1)
                tmax = fmaxf(tmax, __shfl_xor_sync(0xffffffffu, tmax, mm));
            float mnew = fmaxf(m_run[a], tmax);

            float pvals[4];
            float rsum = 0.f;
            #pragma unroll
            for (int b = 0; b < 4; b++) {
                pvals[b] = __expf(fmaf(acc[a][b], 0.125f, -mnew));
                rsum += pvals[b];
            }
            #pragma unroll
            for (int mm = 1; mm <= 8; mm <<= 1)
                rsum += __shfl_xor_sync(0xffffffffu, rsum, mm);

            float c = __expf(m_run[a] - mnew);
            l_run[a] = l_run[a] * c + rsum;
            m_run[a] = mnew;
            #pragma unroll
            for (int b = 0; b < 4; b++) acc_o[a][b] *= c;

            // skewed write: Wt[k = i + l'][i]; complement slots -> 0
            const int i = ty * 4 + a;
            #pragma unroll
            for (int b = 0; b < 4; b++) {
                int k = i + tx * 4 + b;
                Wt[k * WT_STRIDE + i] = pvals[b];
                Wt[((k + 64) & 127) * WT_STRIDE + i] = 0.f;
            }
        }
        __syncthreads();

        // ---- load V band into KV union: Vs[j][d] ----
        {
            const int j0 = tid >> 4;        // 0..15
            const int d4 = tid & 15;
            const float* src = Vg + (size_t)(m0 + lt * BL) * DIM;
            #pragma unroll
            for (int p = 0; p < 8; p++) {
                int jj = p * 16 + j0;
                float4 v = *(const float4*)(src + (size_t)jj * DIM + d4 * 4);
                *(float4*)(KV + jj * 64 + d4 * 4) = v;
            }
        }
        __syncthreads();

        // ---- PV: out[i][d] += sum_k Wt[k][i] * Vs[k][d], banded k-window ----
        {
            const int kstart = ty * 4;      // rows i in [ty*4, ty*4+4) need k in [ty*4, ty*4+68)
            #pragma unroll 4
            for (int ki = 0; ki < 68; ki++) {
                int k = kstart + ki;
                float4 w = *(const float4*)(Wt + k * WT_STRIDE + ty * 4);
                float4 v = *(const float4*)(KV + k * 64 + tx * 4);
                float ww[4] = {w.x,w.y,w.z,w.w};
                float vv[4] = {v.x,v.y,v.z,v.w};
                #pragma unroll
                for (int a = 0; a < 4; a++)
                    #pragma unroll
                    for (int b = 0; b < 4; b++)
                        acc_o[a][b] = fmaf(ww[a], vv[b], acc_o[a][b]);
            }
        }
    }

    // ---- epilogue: normalize and store ----
    #pragma unroll
    for (int a = 0; a < 4; a++) {
        float inv = 1.f / l_run[a];
        int i = ty * 4 + a;
        float4 o;
        o.x = acc_o[a][0] * inv;
        o.y = acc_o[a][1] * inv;
        o.z = acc_o[a][2] * inv;
        o.w = acc_o[a][3] * inv;
        *(float4*)(O + ((size_t)bh * MSEQ + m0 + i) * DIM + tx * 4) = o;
    }
}

extern "C" void kernel_launch(void* const* d_in, const int* in_sizes, int n_in,
                              void* d_out, int out_size) {
    const float* Q = (const float*)d_in[0];
    const float* K = (const float*)d_in[1];
    const float* V = (const float*)d_in[2];
    const float* P = (const float*)d_in[3];
    float* O = (float*)d_out;

    (void)n_in; (void)in_sizes; (void)out_size;

    const size_t smem_bytes = SMEM_FLOATS * sizeof(float);  // 103424 B
    cudaFuncSetAttribute(seqattn_kernel,
                         cudaFuncAttributeMaxDynamicSharedMemorySize,
                         (int)smem_bytes);

    dim3 grid(MSEQ / BM, BH);   // (16, 64)
    seqattn_kernel<<<grid, 256, smem_bytes>>>(Q, K, V, P, O);
}